// round 6
// baseline (speedup 1.0000x reference)
#include <cuda_runtime.h>
#include <cstdint>

// Problem constants
#define BB 64
#define TT 4096
#define CC 51
#define DD 64
#define TPB_TOK 128          // tokens per block
#define NTHREADS 128         // 4 warps, 32 tokens each
#define NGMAX 13             // ceil(52/4) groups of 4 compacted columns
#define LN_EPS 1e-5f

// Packed fp32x2 FMA (Blackwell FFMA2 — PTX-only, ptxas never auto-fuses)
#define FMA2(d, a, b, c) \
    asm("fma.rn.f32x2 %0, %1, %2, %3;" : "=l"(d) : "l"(a), "l"(b), "l"(c))

static __device__ __forceinline__ float lo32(unsigned long long v) {
    return __uint_as_float((unsigned)(v & 0xffffffffull));
}
static __device__ __forceinline__ float hi32(unsigned long long v) {
    return __uint_as_float((unsigned)(v >> 32));
}
static __device__ __forceinline__ unsigned long long pack2(float x, float y) {
    return (unsigned long long)__float_as_uint(x) |
           ((unsigned long long)__float_as_uint(y) << 32);
}

// ---------------------------------------------------------------------------
// Runtime mask-dtype detection: the harness widens jax bool to an unknown
// dtype. Classify by bit pattern of the first 8192 32-bit words of time_mask
// (safe: smallest possible array is 262144 bytes = 65536 words).
//   1 = int32   (words all in {0,1})
//   2 = float32 (words all in {0, 0x3f800000})
//   0 = uint8   (anything else)
// ---------------------------------------------------------------------------
__device__ int g_mask_dtype;

extern "C" __global__ void detect_mask_dtype_kernel(const unsigned* __restrict__ tm)
{
    __shared__ int s_i32, s_f32;
    if (threadIdx.x == 0) { s_i32 = 1; s_f32 = 1; }
    __syncthreads();
    int ok_i32 = 1, ok_f32 = 1;
    for (int i = threadIdx.x; i < 8192; i += blockDim.x) {
        unsigned w = tm[i];
        if (w > 1u)                            ok_i32 = 0;
        if (w != 0u && w != 0x3f800000u)       ok_f32 = 0;
    }
    if (!ok_i32) atomicAnd(&s_i32, 0);
    if (!ok_f32) atomicAnd(&s_f32, 0);
    __syncthreads();
    if (threadIdx.x == 0)
        g_mask_dtype = s_i32 ? 1 : (s_f32 ? 2 : 0);
}

static __device__ __forceinline__ int mask_val(const void* p, long i, int dt)
{
    if (dt == 1) return ((const int*)p)[i] != 0;
    if (dt == 2) return ((const float*)p)[i] != 0.0f;
    return ((const unsigned char*)p)[i] != 0;
}

// LayerNorm over D=64 (2 values per lane) + guarded coalesced store.
// All 32 lanes participate in the shuffles (callers are warp-converged).
static __device__ __forceinline__ void ln_store(unsigned long long a, bool valid,
                                                float2* dst, float2 g2, float2 b2)
{
    float ax = lo32(a), ay = hi32(a);
    float s = ax + ay;
    float q = ax * ax + ay * ay;
#pragma unroll
    for (int o = 16; o > 0; o >>= 1) {
        s += __shfl_xor_sync(0xffffffffu, s, o);
        q += __shfl_xor_sync(0xffffffffu, q, o);
    }
    float mu  = s * (1.0f / 64.0f);
    float var = fmaf(-mu, mu, q * (1.0f / 64.0f));
    float r   = rsqrtf(var + LN_EPS);
    if (valid) {
        float2 o2;
        o2.x = fmaf((ax - mu) * r, g2.x, b2.x);
        o2.y = fmaf((ay - mu) * r, g2.y, b2.y);
        *dst = o2;
    }
}

// Dynamic shared memory layout (bytes):
//   [0)        float2 xs[128][52]   duplicated (x,x) pairs  = 53248
//   [53248)    uchar  tm_sh[128]
//   [53376)    uchar  sm_sh[64]
//   [53440)    int    cmap[52]
//   [53648)    int    cpos[52]
//   [53856)    int    nc
#define SMEM_XS    0
#define SMEM_TM    (128 * 52 * 8)
#define SMEM_SM    (SMEM_TM + 128)
#define SMEM_CMAP  (SMEM_SM + 64)
#define SMEM_CPOS  (SMEM_CMAP + 52 * 4)
#define SMEM_NC    (SMEM_CPOS + 52 * 4)
#define SMEM_TOTAL (SMEM_NC + 16)

extern "C" __global__ void __launch_bounds__(NTHREADS)
fused_proj_ln_kernel(const float* __restrict__ x,
                     const float* __restrict__ W,
                     const float* __restrict__ Wm,
                     const float* __restrict__ gamma,
                     const float* __restrict__ beta,
                     const void* __restrict__ time_mask,
                     const void* __restrict__ sensor_mask,
                     float* __restrict__ out)
{
    extern __shared__ char smem[];
    float2*        xs    = (float2*)(smem + SMEM_XS);          // [128][52]
    unsigned char* tm_sh = (unsigned char*)(smem + SMEM_TM);
    unsigned char* sm_sh = (unsigned char*)(smem + SMEM_SM);
    int*           cmap  = (int*)(smem + SMEM_CMAP);
    int*           cpos  = (int*)(smem + SMEM_CPOS);
    int*           ncp   = (int*)(smem + SMEM_NC);

    const int tid  = threadIdx.x;
    const int lane = tid & 31;
    const int wid  = tid >> 5;

    const int  blocksPerBatch = TT / TPB_TOK;                  // 32
    const int  b    = blockIdx.x / blocksPerBatch;
    const int  tb   = (blockIdx.x % blocksPerBatch) * TPB_TOK;
    const long tok0 = (long)b * TT + tb;

    const int dt = g_mask_dtype;   // uniform; written by detection kernel

    // ---- stage masks ----
    if (tid < CC) sm_sh[tid] = (unsigned char)mask_val(sensor_mask, (long)b * CC + tid, dt);
    tm_sh[tid] = (unsigned char)mask_val(time_mask, tok0 + tid, dt);
    __syncthreads();

    // ---- build compacted column maps (single writer) ----
    if (tid == 0) {
        int n = 0;
#pragma unroll
        for (int c = 0; c < CC; ++c) {
            int p = -1;
            if (!sm_sh[c]) { cmap[n] = c; p = n; ++n; }
            cpos[c] = p;
        }
        *ncp = n;
    }
    __syncthreads();

    const int nc = *ncp;
    const int NG = (nc + 3) >> 2;     // active 4-column groups (block-uniform)

    // ---- zero the compacted pad region of this thread's row ----
    {
        float2 z = make_float2(0.f, 0.f);
        for (int k = nc; k < 4 * NG; ++k) xs[tid * 52 + k] = z;
    }

    // ---- stage x: coalesced global reads, compacted + duplicated SMEM writes ----
    {
        const float* xg = x + tok0 * CC;
        int g   = tid;
        int row = g / CC;
        int col = g - row * CC;
#pragma unroll 1
        for (int it = 0; it < CC; ++it) {   // 51*128 == 128*51 exactly
            float v = xg[g];
            int j = cpos[col];
            if (j >= 0) xs[row * 52 + j] = make_float2(v, v);
            g += NTHREADS;
            col += NTHREADS - 2 * CC;       // +26
            row += 2;
            if (col >= CC) { col -= CC; ++row; }
        }
    }

    // ---- per-lane register W (compacted, packed float2 for d=2l,2l+1) ----
    unsigned long long Wreg[52];
#pragma unroll
    for (int j = 0; j < 52; ++j) {
        unsigned long long w = 0ull;
        if (j < nc) {
            int c = cmap[j];
            w = *(const unsigned long long*)(W + c * DD + 2 * lane);
        }
        Wreg[j] = w;
    }

    // ---- per-batch bias (sum Wm over sensor-masked c) and global Wm sum ----
    float2 bias = make_float2(0.f, 0.f);
    float2 wsum = make_float2(0.f, 0.f);
#pragma unroll 1
    for (int c = 0; c < CC; ++c) {
        float2 wm = *(const float2*)(Wm + c * DD + 2 * lane);
        wsum.x += wm.x; wsum.y += wm.y;
        if (sm_sh[c]) { bias.x += wm.x; bias.y += wm.y; }
    }

    float2 g2 = *(const float2*)(gamma + 2 * lane);
    float2 b2 = *(const float2*)(beta  + 2 * lane);

    // ---- constant output row for time-masked tokens: LN(sum_all_c Wm) ----
    float2 cvec;
    {
        float s = wsum.x + wsum.y;
        float q = wsum.x * wsum.x + wsum.y * wsum.y;
#pragma unroll
        for (int o = 16; o > 0; o >>= 1) {
            s += __shfl_xor_sync(0xffffffffu, s, o);
            q += __shfl_xor_sync(0xffffffffu, q, o);
        }
        float mu  = s * (1.0f / 64.0f);
        float var = fmaf(-mu, mu, q * (1.0f / 64.0f));
        float r   = rsqrtf(var + LN_EPS);
        cvec.x = fmaf((wsum.x - mu) * r, g2.x, b2.x);
        cvec.y = fmaf((wsum.y - mu) * r, g2.y, b2.y);
    }
    __syncthreads();   // xs / tm_sh staging complete

    // ---- mainloop: each warp owns 32 consecutive tokens ----
    float2*    out2  = (float2*)out;
    const int  rbase = wid * 32;
    const long otok  = tok0 + rbase;
    const unsigned long long bll = pack2(bias.x, bias.y);

    unsigned um = __ballot_sync(0xffffffffu, tm_sh[rbase + lane] == 0);
    unsigned mm = ~um;

    // time-masked tokens: one coalesced constant-row store each
    while (mm) {
        int i = __ffs((int)mm) - 1; mm &= mm - 1;
        out2[(otok + i) * 32 + lane] = cvec;
    }

    // unmasked tokens: warp-compacted groups of 4 (4 independent FFMA2 chains)
    while (um) {
        int r0 = __ffs((int)um) - 1; um &= um - 1;
        int r1 = r0, r2 = r0, r3 = r0;
        int nv = 1;
        if (um) { r1 = __ffs((int)um) - 1; um &= um - 1; nv = 2; }
        if (um) { r2 = __ffs((int)um) - 1; um &= um - 1; nv = 3; }
        if (um) { r3 = __ffs((int)um) - 1; um &= um - 1; nv = 4; }

        const ulonglong2* p0 = (const ulonglong2*)(xs + (rbase + r0) * 52);
        const ulonglong2* p1 = (const ulonglong2*)(xs + (rbase + r1) * 52);
        const ulonglong2* p2 = (const ulonglong2*)(xs + (rbase + r2) * 52);
        const ulonglong2* p3 = (const ulonglong2*)(xs + (rbase + r3) * 52);

        unsigned long long a0 = bll, a1 = bll, a2 = bll, a3 = bll;

#pragma unroll
        for (int gi = 0; gi < NGMAX; ++gi) {
            if (gi < NG) {
                ulonglong2 u0 = p0[2 * gi], v0 = p0[2 * gi + 1];
                ulonglong2 u1 = p1[2 * gi], v1 = p1[2 * gi + 1];
                ulonglong2 u2 = p2[2 * gi], v2 = p2[2 * gi + 1];
                ulonglong2 u3 = p3[2 * gi], v3 = p3[2 * gi + 1];

                FMA2(a0, u0.x, Wreg[4 * gi + 0], a0);
                FMA2(a1, u1.x, Wreg[4 * gi + 0], a1);
                FMA2(a2, u2.x, Wreg[4 * gi + 0], a2);
                FMA2(a3, u3.x, Wreg[4 * gi + 0], a3);

                FMA2(a0, u0.y, Wreg[4 * gi + 1], a0);
                FMA2(a1, u1.y, Wreg[4 * gi + 1], a1);
                FMA2(a2, u2.y, Wreg[4 * gi + 1], a2);
                FMA2(a3, u3.y, Wreg[4 * gi + 1], a3);

                FMA2(a0, v0.x, Wreg[4 * gi + 2], a0);
                FMA2(a1, v1.x, Wreg[4 * gi + 2], a1);
                FMA2(a2, v2.x, Wreg[4 * gi + 2], a2);
                FMA2(a3, v3.x, Wreg[4 * gi + 2], a3);

                FMA2(a0, v0.y, Wreg[4 * gi + 3], a0);
                FMA2(a1, v1.y, Wreg[4 * gi + 3], a1);
                FMA2(a2, v2.y, Wreg[4 * gi + 3], a2);
                FMA2(a3, v3.y, Wreg[4 * gi + 3], a3);
            }
        }

        ln_store(a0, true,    out2 + (otok + r0) * 32 + lane, g2, b2);
        ln_store(a1, nv > 1,  out2 + (otok + r1) * 32 + lane, g2, b2);
        ln_store(a2, nv > 2,  out2 + (otok + r2) * 32 + lane, g2, b2);
        ln_store(a3, nv > 3,  out2 + (otok + r3) * 32 + lane, g2, b2);
    }
}

extern "C" void kernel_launch(void* const* d_in, const int* in_sizes, int n_in,
                              void* d_out, int out_size)
{
    const float* x     = (const float*)d_in[0];
    const float* W     = (const float*)d_in[1];
    const float* Wm    = (const float*)d_in[2];
    const float* gamma = (const float*)d_in[3];
    const float* beta  = (const float*)d_in[4];
    const void*  tmask = d_in[5];
    const void*  smask = d_in[6];

    (void)in_sizes; (void)n_in; (void)out_size;

    cudaFuncSetAttribute(fused_proj_ln_kernel,
                         cudaFuncAttributeMaxDynamicSharedMemorySize, SMEM_TOTAL);

    detect_mask_dtype_kernel<<<1, 1024>>>((const unsigned*)tmask);

    const int nblocks = (BB * TT) / TPB_TOK;   // 2048
    fused_proj_ln_kernel<<<nblocks, NTHREADS, SMEM_TOTAL>>>(
        x, W, Wm, gamma, beta, tmask, smask, (float*)d_out);
}

// round 7
// speedup vs baseline: 1.7608x; 1.7608x over previous
#include <cuda_runtime.h>
#include <cstdint>

// Problem constants
#define BB 64
#define TT 4096
#define CC 51
#define DD 64
#define NTHREADS 128            // 4 warps; each warp owns 32 tokens of a tile
#define TILES_PER_BLOCK 2
#define BLOCKS_PER_BATCH 16     // 16 blocks * 2 tiles * 128 tokens = 4096 = TT
#define LN_EPS 1e-5f

// Packed fp32x2 FMA (Blackwell FFMA2 — PTX-only, ptxas never auto-fuses)
#define FMA2(d, a, b, c) \
    asm("fma.rn.f32x2 %0, %1, %2, %3;" : "=l"(d) : "l"(a), "l"(b), "l"(c))

static __device__ __forceinline__ float lo32(unsigned long long v) {
    return __uint_as_float((unsigned)(v & 0xffffffffull));
}
static __device__ __forceinline__ float hi32(unsigned long long v) {
    return __uint_as_float((unsigned)(v >> 32));
}
static __device__ __forceinline__ unsigned long long pack2(float x, float y) {
    return (unsigned long long)__float_as_uint(x) |
           ((unsigned long long)__float_as_uint(y) << 32);
}

// ---------------------------------------------------------------------------
// Runtime mask-dtype detection (harness widens jax bool; classify bit pattern).
//   1 = int32 {0,1}   2 = float32 {0,1.0f}   0 = uint8
// ---------------------------------------------------------------------------
__device__ int g_mask_dtype;

extern "C" __global__ void detect_mask_dtype_kernel(const unsigned* __restrict__ tm)
{
    __shared__ int s_i32, s_f32;
    if (threadIdx.x == 0) { s_i32 = 1; s_f32 = 1; }
    __syncthreads();
    int ok_i32 = 1, ok_f32 = 1;
    for (int i = threadIdx.x; i < 8192; i += blockDim.x) {
        unsigned w = tm[i];
        if (w > 1u)                      ok_i32 = 0;
        if (w != 0u && w != 0x3f800000u) ok_f32 = 0;
    }
    if (!ok_i32) atomicAnd(&s_i32, 0);
    if (!ok_f32) atomicAnd(&s_f32, 0);
    __syncthreads();
    if (threadIdx.x == 0)
        g_mask_dtype = s_i32 ? 1 : (s_f32 ? 2 : 0);
}

static __device__ __forceinline__ int mask_val(const void* p, long i, int dt)
{
    if (dt == 1) return ((const int*)p)[i] != 0;
    if (dt == 2) return ((const float*)p)[i] != 0.0f;
    return ((const unsigned char*)p)[i] != 0;
}

// ---------------------------------------------------------------------------
// Fused LayerNorm for 4 accumulators (interleaved shuffles overlap SHFL lat).
// All 32 lanes participate; stores guarded by nv.
// ---------------------------------------------------------------------------
static __device__ __forceinline__ void ln_store4(
    unsigned long long a0, unsigned long long a1,
    unsigned long long a2, unsigned long long a3,
    int nv, float2* d0, float2* d1, float2* d2, float2* d3,
    float2 g2, float2 b2)
{
    float x0 = lo32(a0), y0 = hi32(a0);
    float x1 = lo32(a1), y1 = hi32(a1);
    float x2 = lo32(a2), y2 = hi32(a2);
    float x3 = lo32(a3), y3 = hi32(a3);

    float s0 = x0 + y0, q0 = x0 * x0 + y0 * y0;
    float s1 = x1 + y1, q1 = x1 * x1 + y1 * y1;
    float s2 = x2 + y2, q2 = x2 * x2 + y2 * y2;
    float s3 = x3 + y3, q3 = x3 * x3 + y3 * y3;

#pragma unroll
    for (int o = 16; o > 0; o >>= 1) {
        s0 += __shfl_xor_sync(0xffffffffu, s0, o);
        s1 += __shfl_xor_sync(0xffffffffu, s1, o);
        s2 += __shfl_xor_sync(0xffffffffu, s2, o);
        s3 += __shfl_xor_sync(0xffffffffu, s3, o);
        q0 += __shfl_xor_sync(0xffffffffu, q0, o);
        q1 += __shfl_xor_sync(0xffffffffu, q1, o);
        q2 += __shfl_xor_sync(0xffffffffu, q2, o);
        q3 += __shfl_xor_sync(0xffffffffu, q3, o);
    }

    float mu0 = s0 * (1.f/64.f), r0 = rsqrtf(fmaf(-mu0, mu0, q0 * (1.f/64.f)) + LN_EPS);
    float mu1 = s1 * (1.f/64.f), r1 = rsqrtf(fmaf(-mu1, mu1, q1 * (1.f/64.f)) + LN_EPS);
    float mu2 = s2 * (1.f/64.f), r2 = rsqrtf(fmaf(-mu2, mu2, q2 * (1.f/64.f)) + LN_EPS);
    float mu3 = s3 * (1.f/64.f), r3 = rsqrtf(fmaf(-mu3, mu3, q3 * (1.f/64.f)) + LN_EPS);

    float2 o0, o1, o2, o3;
    o0.x = fmaf((x0 - mu0) * r0, g2.x, b2.x);  o0.y = fmaf((y0 - mu0) * r0, g2.y, b2.y);
    o1.x = fmaf((x1 - mu1) * r1, g2.x, b2.x);  o1.y = fmaf((y1 - mu1) * r1, g2.y, b2.y);
    o2.x = fmaf((x2 - mu2) * r2, g2.x, b2.x);  o2.y = fmaf((y2 - mu2) * r2, g2.y, b2.y);
    o3.x = fmaf((x3 - mu3) * r3, g2.x, b2.x);  o3.y = fmaf((y3 - mu3) * r3, g2.y, b2.y);

    *d0 = o0;
    if (nv > 1) *d1 = o1;
    if (nv > 2) *d2 = o2;
    if (nv > 3) *d3 = o3;
}

// Dynamic shared memory layout (bytes):
//   [0)       float2 xs[128][52]  duplicated (x,x) pairs = 53248
//   [53248)   uchar  sm_sh[64]
//   [53312)   uchar  tm_sh[128]
#define SMEM_XS    0
#define SMEM_SM    (128 * 52 * 8)
#define SMEM_TM    (SMEM_SM + 64)
#define SMEM_TOTAL (SMEM_TM + 128)

extern "C" __global__ void __launch_bounds__(NTHREADS)
fused_proj_ln_kernel(const float* __restrict__ x,
                     const float* __restrict__ W,
                     const float* __restrict__ Wm,
                     const float* __restrict__ gamma,
                     const float* __restrict__ beta,
                     const void* __restrict__ time_mask,
                     const void* __restrict__ sensor_mask,
                     float* __restrict__ out)
{
    extern __shared__ char smem[];
    float2*        xs    = (float2*)(smem + SMEM_XS);   // [128][52]
    unsigned char* sm_sh = (unsigned char*)(smem + SMEM_SM);
    unsigned char* tm_sh = (unsigned char*)(smem + SMEM_TM);

    const int tid  = threadIdx.x;
    const int lane = tid & 31;
    const int wid  = tid >> 5;

    const int b      = blockIdx.x / BLOCKS_PER_BATCH;
    const int ktile0 = (blockIdx.x % BLOCKS_PER_BATCH) * TILES_PER_BLOCK;
    const int dt     = g_mask_dtype;

    // ================= prologue (once per block, amortized over 2 tiles) =====
    if (tid < CC) sm_sh[tid] = (unsigned char)mask_val(sensor_mask, (long)b * CC + tid, dt);
    // zero the single pad column (col 51) of this thread's xs row — persists
    xs[tid * 52 + 51] = make_float2(0.f, 0.f);
    __syncthreads();

    // Per-lane W (d = 2*lane, 2*lane+1), sensor-masked columns zeroed, col 51 pad zero.
    unsigned long long Wreg[52];
#pragma unroll
    for (int c = 0; c < 52; ++c) {
        unsigned long long w = 0ull;
        if (c < CC) {
            w = *(const unsigned long long*)(W + c * DD + 2 * lane);
            if (sm_sh[c]) w = 0ull;
        }
        Wreg[c] = w;
    }

    // Per-batch bias (sum Wm over sensor-masked c) and global Wm sum (dual accumulators).
    float2 wsA = make_float2(0.f, 0.f), wsB = make_float2(0.f, 0.f);
    float2 bsA = make_float2(0.f, 0.f), bsB = make_float2(0.f, 0.f);
#pragma unroll
    for (int c = 0; c < CC; ++c) {
        float2 wm = *(const float2*)(Wm + c * DD + 2 * lane);
        if (c & 1) { wsB.x += wm.x; wsB.y += wm.y; if (sm_sh[c]) { bsB.x += wm.x; bsB.y += wm.y; } }
        else       { wsA.x += wm.x; wsA.y += wm.y; if (sm_sh[c]) { bsA.x += wm.x; bsA.y += wm.y; } }
    }
    float2 wsum = make_float2(wsA.x + wsB.x, wsA.y + wsB.y);
    float2 bias = make_float2(bsA.x + bsB.x, bsA.y + bsB.y);

    const float2 g2 = *(const float2*)(gamma + 2 * lane);
    const float2 b2 = *(const float2*)(beta  + 2 * lane);
    const unsigned long long bll = pack2(bias.x, bias.y);

    // Constant output row for time-masked tokens: LN(sum_all_c Wm).
    float2 cvec;
    {
        float s = wsum.x + wsum.y;
        float q = wsum.x * wsum.x + wsum.y * wsum.y;
#pragma unroll
        for (int o = 16; o > 0; o >>= 1) {
            s += __shfl_xor_sync(0xffffffffu, s, o);
            q += __shfl_xor_sync(0xffffffffu, q, o);
        }
        float mu  = s * (1.0f / 64.0f);
        float r   = rsqrtf(fmaf(-mu, mu, q * (1.0f / 64.0f)) + LN_EPS);
        cvec.x = fmaf((wsum.x - mu) * r, g2.x, b2.x);
        cvec.y = fmaf((wsum.y - mu) * r, g2.y, b2.y);
    }

    float2* out2 = (float2*)out;

    // ================= tile loop =============================================
    for (int tile = 0; tile < TILES_PER_BLOCK; ++tile) {
        const int  tb   = (ktile0 + tile) * 128;
        const long tok0 = (long)b * TT + tb;

        // ---- stage time mask ----
        tm_sh[tid] = (unsigned char)mask_val(time_mask, tok0 + tid, dt);

        // ---- stage x: vectorized float4 global reads (16B-aligned slab),
        //      duplicated (x,x) SMEM writes, identity column layout ----
        {
            const float4* xg4 = (const float4*)(x + tok0 * CC);  // 1632 float4 per tile
#pragma unroll 1
            for (int i = tid; i < (128 * CC) / 4; i += NTHREADS) {
                float4 v = xg4[i];
                int idx = 4 * i;
                int row = idx / CC;
                int col = idx - row * CC;
                float2* xr = xs + row * 52;
                xr[col] = make_float2(v.x, v.x);
                if (++col == CC) { col = 0; xr += 52; }
                xr[col] = make_float2(v.y, v.y);
                if (++col == CC) { col = 0; xr += 52; }
                xr[col] = make_float2(v.z, v.z);
                if (++col == CC) { col = 0; xr += 52; }
                xr[col] = make_float2(v.w, v.w);
            }
        }
        __syncthreads();

        // ---- compute: each warp owns 32 consecutive tokens ----
        const int  rbase = wid * 32;
        const long otok  = tok0 + rbase;

        unsigned um = __ballot_sync(0xffffffffu, tm_sh[rbase + lane] == 0);
        unsigned mm = ~um;

        // time-masked tokens: straight-line predicated constant-row stores
        {
            float2* ob = out2 + otok * 32 + lane;
#pragma unroll
            for (int r = 0; r < 32; ++r)
                if ((mm >> r) & 1u) ob[r * 32] = cvec;
        }

        // unmasked tokens: warp-compacted groups of 4 (4 independent FFMA2 chains,
        // branch-free static 13-group inner loop)
        while (um) {
            int r0 = __ffs((int)um) - 1; um &= um - 1;
            int r1 = r0, r2 = r0, r3 = r0;
            int nv = 1;
            if (um) { r1 = __ffs((int)um) - 1; um &= um - 1; nv = 2; }
            if (um) { r2 = __ffs((int)um) - 1; um &= um - 1; nv = 3; }
            if (um) { r3 = __ffs((int)um) - 1; um &= um - 1; nv = 4; }

            const ulonglong2* p0 = (const ulonglong2*)(xs + (rbase + r0) * 52);
            const ulonglong2* p1 = (const ulonglong2*)(xs + (rbase + r1) * 52);
            const ulonglong2* p2 = (const ulonglong2*)(xs + (rbase + r2) * 52);
            const ulonglong2* p3 = (const ulonglong2*)(xs + (rbase + r3) * 52);

            unsigned long long a0 = bll, a1 = bll, a2 = bll, a3 = bll;

#pragma unroll
            for (int gi = 0; gi < 13; ++gi) {
                ulonglong2 u0 = p0[2 * gi], v0 = p0[2 * gi + 1];
                ulonglong2 u1 = p1[2 * gi], v1 = p1[2 * gi + 1];
                ulonglong2 u2 = p2[2 * gi], v2 = p2[2 * gi + 1];
                ulonglong2 u3 = p3[2 * gi], v3 = p3[2 * gi + 1];

                FMA2(a0, u0.x, Wreg[4 * gi + 0], a0);
                FMA2(a1, u1.x, Wreg[4 * gi + 0], a1);
                FMA2(a2, u2.x, Wreg[4 * gi + 0], a2);
                FMA2(a3, u3.x, Wreg[4 * gi + 0], a3);

                FMA2(a0, u0.y, Wreg[4 * gi + 1], a0);
                FMA2(a1, u1.y, Wreg[4 * gi + 1], a1);
                FMA2(a2, u2.y, Wreg[4 * gi + 1], a2);
                FMA2(a3, u3.y, Wreg[4 * gi + 1], a3);

                FMA2(a0, v0.x, Wreg[4 * gi + 2], a0);
                FMA2(a1, v1.x, Wreg[4 * gi + 2], a1);
                FMA2(a2, v2.x, Wreg[4 * gi + 2], a2);
                FMA2(a3, v3.x, Wreg[4 * gi + 2], a3);

                FMA2(a0, v0.y, Wreg[4 * gi + 3], a0);
                FMA2(a1, v1.y, Wreg[4 * gi + 3], a1);
                FMA2(a2, v2.y, Wreg[4 * gi + 3], a2);
                FMA2(a3, v3.y, Wreg[4 * gi + 3], a3);
            }

            ln_store4(a0, a1, a2, a3, nv,
                      out2 + (otok + r0) * 32 + lane,
                      out2 + (otok + r1) * 32 + lane,
                      out2 + (otok + r2) * 32 + lane,
                      out2 + (otok + r3) * 32 + lane,
                      g2, b2);
        }

        __syncthreads();   // xs/tm_sh consumed — safe to restage next tile
    }
}

extern "C" void kernel_launch(void* const* d_in, const int* in_sizes, int n_in,
                              void* d_out, int out_size)
{
    const float* x     = (const float*)d_in[0];
    const float* W     = (const float*)d_in[1];
    const float* Wm    = (const float*)d_in[2];
    const float* gamma = (const float*)d_in[3];
    const float* beta  = (const float*)d_in[4];
    const void*  tmask = d_in[5];
    const void*  smask = d_in[6];

    (void)in_sizes; (void)n_in; (void)out_size;

    cudaFuncSetAttribute(fused_proj_ln_kernel,
                         cudaFuncAttributeMaxDynamicSharedMemorySize, SMEM_TOTAL);

    detect_mask_dtype_kernel<<<1, 1024>>>((const unsigned*)tmask);

    const int nblocks = BB * BLOCKS_PER_BATCH;   // 1024
    fused_proj_ln_kernel<<<nblocks, NTHREADS, SMEM_TOTAL>>>(
        x, W, Wm, gamma, beta, tmask, smask, (float*)d_out);
}

// round 8
// speedup vs baseline: 2.3683x; 1.3450x over previous
#include <cuda_runtime.h>
#include <cstdint>

#define BB 64
#define TT 4096
#define CC 51
#define DD 64
#define NTHREADS 128
#define LN_EPS 1e-5f

typedef unsigned long long ull;

// Packed fp32x2 FMA (Blackwell FFMA2 — PTX-only)
#define FMA2(d, a, b, c) \
    asm("fma.rn.f32x2 %0, %1, %2, %3;" : "=l"(d) : "l"(a), "l"(b), "l"(c))

static __device__ __forceinline__ float lo32(ull v) { return __uint_as_float((unsigned)v); }
static __device__ __forceinline__ float hi32(ull v) { return __uint_as_float((unsigned)(v >> 32)); }
static __device__ __forceinline__ ull pack2(float x, float y) {
    return (ull)__float_as_uint(x) | ((ull)__float_as_uint(y) << 32);
}

// ---------------------------------------------------------------------------
// Runtime mask-dtype detection (harness widens jax bool; classify bit pattern)
//   1 = int32 {0,1}   2 = float32 {0,1.0f}   0 = uint8
// ---------------------------------------------------------------------------
__device__ int  g_mask_dtype;
__device__ ull    g_biasll[BB * 32];   // per (batch, lane): packed sum of masked Wm
__device__ float2 g_cvecv[BB * 32];    // per (batch, lane): LN(sum_all Wm) constant row

extern "C" __global__ void detect_mask_dtype_kernel(const unsigned* __restrict__ tm)
{
    __shared__ int s_i32, s_f32;
    if (threadIdx.x == 0) { s_i32 = 1; s_f32 = 1; }
    __syncthreads();
    int ok_i32 = 1, ok_f32 = 1;
    for (int i = threadIdx.x; i < 8192; i += blockDim.x) {
        unsigned w = tm[i];
        if (w > 1u)                      ok_i32 = 0;
        if (w != 0u && w != 0x3f800000u) ok_f32 = 0;
    }
    if (!ok_i32) atomicAnd(&s_i32, 0);
    if (!ok_f32) atomicAnd(&s_f32, 0);
    __syncthreads();
    if (threadIdx.x == 0)
        g_mask_dtype = s_i32 ? 1 : (s_f32 ? 2 : 0);
}

static __device__ __forceinline__ int mask_val(const void* p, long i, int dt)
{
    if (dt == 1) return ((const int*)p)[i] != 0;
    if (dt == 2) return ((const float*)p)[i] != 0.0f;
    return ((const unsigned char*)p)[i] != 0;
}

// ---------------------------------------------------------------------------
// Per-batch precompute: bias = sum_{c masked} Wm[c,:],  cvec = LN(sum_all Wm)
// grid = 64 batches, block = 32 lanes (lane owns d = 2l, 2l+1)
// ---------------------------------------------------------------------------
extern "C" __global__ void precompute_batch_kernel(const float* __restrict__ Wm,
                                                   const void* __restrict__ smask,
                                                   const float* __restrict__ gamma,
                                                   const float* __restrict__ beta)
{
    const int b = blockIdx.x, lane = threadIdx.x;
    const int dt = g_mask_dtype;
    float2 ws = make_float2(0.f, 0.f), bs = make_float2(0.f, 0.f);
#pragma unroll
    for (int c = 0; c < CC; ++c) {
        float2 wm = *(const float2*)(Wm + c * DD + 2 * lane);
        ws.x += wm.x; ws.y += wm.y;
        if (mask_val(smask, (long)b * CC + c, dt)) { bs.x += wm.x; bs.y += wm.y; }
    }
    float2 g2 = *(const float2*)(gamma + 2 * lane);
    float2 b2 = *(const float2*)(beta  + 2 * lane);
    float s = ws.x + ws.y, q = ws.x * ws.x + ws.y * ws.y;
#pragma unroll
    for (int o = 16; o > 0; o >>= 1) {
        s += __shfl_xor_sync(0xffffffffu, s, o);
        q += __shfl_xor_sync(0xffffffffu, q, o);
    }
    float mu = s * (1.f / 64.f);
    float r  = rsqrtf(fmaf(-mu, mu, q * (1.f / 64.f)) + LN_EPS);
    float2 cv;
    cv.x = fmaf((ws.x - mu) * r, g2.x, b2.x);
    cv.y = fmaf((ws.y - mu) * r, g2.y, b2.y);
    g_biasll[b * 32 + lane] = pack2(bs.x, bs.y);
    g_cvecv[b * 32 + lane]  = cv;
}

// ---------------------------------------------------------------------------
// Main kernel. SMEM layout (bytes):
//   [0)      ull  xs[128][52]          duplicated (x,x) pairs      = 53248
//   [53248)  ulonglong2 Wsh2[26][32]   W col-pairs, per-lane d     = 13312
//   [66560)  uchar tm_sh[128]
//   [66688)  uchar sm_sh[64]
// ---------------------------------------------------------------------------
#define SMEM_XS   0
#define SMEM_WSH  53248
#define SMEM_TM   66560
#define SMEM_SM   66688
#define SMEM_TOTAL 66752

extern "C" __global__ void __launch_bounds__(NTHREADS, 3)
fused_proj_ln_kernel(const float* __restrict__ x,
                     const float* __restrict__ W,
                     const float* __restrict__ gamma,
                     const float* __restrict__ beta,
                     const void* __restrict__ time_mask,
                     const void* __restrict__ sensor_mask,
                     float* __restrict__ out)
{
    extern __shared__ char smem[];
    ull*           xs    = (ull*)(smem + SMEM_XS);            // [128][52]
    ulonglong2*    Wsh2  = (ulonglong2*)(smem + SMEM_WSH);    // [26][32]
    unsigned char* tm_sh = (unsigned char*)(smem + SMEM_TM);
    unsigned char* sm_sh = (unsigned char*)(smem + SMEM_SM);

    const int tid  = threadIdx.x;
    const int lane = tid & 31;
    const int wid  = tid >> 5;

    const int  b    = blockIdx.x >> 5;              // 32 blocks per batch
    const int  tb   = (blockIdx.x & 31) * 128;
    const long tok0 = (long)b * TT + tb;
    const int  dt   = g_mask_dtype;

    // ---- stage sensor mask ----
    if (tid < CC) sm_sh[tid] = (unsigned char)mask_val(sensor_mask, (long)b * CC + tid, dt);
    __syncthreads();

    // ---- W -> SMEM: interleaved column-pair layout, masked columns zeroed ----
    for (int j = wid; j < 26; j += 4) {
        int c0 = 2 * j, c1 = 2 * j + 1;
        ull w0 = sm_sh[c0] ? 0ull : *(const ull*)(W + c0 * DD + 2 * lane);
        ull w1 = (c1 < CC && !sm_sh[c1]) ? *(const ull*)(W + c1 * DD + 2 * lane) : 0ull;
        ulonglong2 t; t.x = w0; t.y = w1;
        Wsh2[j * 32 + lane] = t;
    }

    // ---- pad column + time mask ----
    xs[tid * 52 + 51] = 0ull;
    tm_sh[tid] = (unsigned char)mask_val(time_mask, tok0 + tid, dt);

    // ---- stage x: 12-deep MLP batched LDG.128, duplicated SMEM scatter ----
    {
        const float4* xg4 = (const float4*)(x + tok0 * CC);   // 1632 float4 per tile
        float4 vv[13];
#pragma unroll
        for (int k = 0; k < 12; ++k) vv[k] = xg4[tid + 128 * k];
        const bool tail = tid < 96;                            // 1632 - 1536
        if (tail) vv[12] = xg4[1536 + tid];
#pragma unroll
        for (int k = 0; k < 13; ++k) {
            if (k < 12 || tail) {
                int idx = 4 * tid + 512 * k;
                int row = idx / CC;
                int col = idx - row * CC;
                ull* xr = xs + row * 52;
                xr[col] = pack2(vv[k].x, vv[k].x);
                if (++col == CC) { col = 0; xr += 52; }
                xr[col] = pack2(vv[k].y, vv[k].y);
                if (++col == CC) { col = 0; xr += 52; }
                xr[col] = pack2(vv[k].z, vv[k].z);
                if (++col == CC) { col = 0; xr += 52; }
                xr[col] = pack2(vv[k].w, vv[k].w);
            }
        }
    }

    // ---- per-lane constants (precomputed per batch) ----
    const ull    bll  = g_biasll[b * 32 + lane];
    const float2 cvec = g_cvecv[b * 32 + lane];
    const float2 g2   = *(const float2*)(gamma + 2 * lane);
    const float2 b2   = *(const float2*)(beta  + 2 * lane);
    __syncthreads();

    // ---- each warp owns 32 consecutive tokens ----
    const int  rbase = wid * 32;
    float2*    outw  = (float2*)out + (tok0 + rbase) * 32 + lane;

    unsigned um = __ballot_sync(0xffffffffu, tm_sh[rbase + lane] == 0);
    unsigned mm = ~um;

    // time-masked tokens: predicated constant-row stores
#pragma unroll
    for (int r = 0; r < 32; ++r)
        if ((mm >> r) & 1u) outw[r * 32] = cvec;

    // unmasked tokens: warp-compacted groups of 8 (8 independent FFMA2 chains)
    while (um) {
        int r0 = __ffs(um) - 1; um &= um - 1;
        int r1 = r0, r2 = r0, r3 = r0, r4 = r0, r5 = r0, r6 = r0, r7 = r0;
        int nv = 1;
        if (um) { r1 = __ffs(um) - 1; um &= um - 1; nv = 2; }
        if (um) { r2 = __ffs(um) - 1; um &= um - 1; nv = 3; }
        if (um) { r3 = __ffs(um) - 1; um &= um - 1; nv = 4; }
        if (um) { r4 = __ffs(um) - 1; um &= um - 1; nv = 5; }
        if (um) { r5 = __ffs(um) - 1; um &= um - 1; nv = 6; }
        if (um) { r6 = __ffs(um) - 1; um &= um - 1; nv = 7; }
        if (um) { r7 = __ffs(um) - 1; um &= um - 1; nv = 8; }

        const ulonglong2* p0 = (const ulonglong2*)(xs + (rbase + r0) * 52);
        const ulonglong2* p1 = (const ulonglong2*)(xs + (rbase + r1) * 52);
        const ulonglong2* p2 = (const ulonglong2*)(xs + (rbase + r2) * 52);
        const ulonglong2* p3 = (const ulonglong2*)(xs + (rbase + r3) * 52);
        const ulonglong2* p4 = (const ulonglong2*)(xs + (rbase + r4) * 52);
        const ulonglong2* p5 = (const ulonglong2*)(xs + (rbase + r5) * 52);
        const ulonglong2* p6 = (const ulonglong2*)(xs + (rbase + r6) * 52);
        const ulonglong2* p7 = (const ulonglong2*)(xs + (rbase + r7) * 52);

        ull a0 = bll, a1 = bll, a2 = bll, a3 = bll;
        ull a4 = bll, a5 = bll, a6 = bll, a7 = bll;

#pragma unroll
        for (int gi = 0; gi < 13; ++gi) {
            ulonglong2 wA = Wsh2[(2 * gi) * 32 + lane];       // cols 4gi, 4gi+1
            ulonglong2 wB = Wsh2[(2 * gi + 1) * 32 + lane];   // cols 4gi+2, 4gi+3
            {
                ulonglong2 u = p0[2 * gi], v = p0[2 * gi + 1];
                FMA2(a0, u.x, wA.x, a0); FMA2(a0, u.y, wA.y, a0);
                FMA2(a0, v.x, wB.x, a0); FMA2(a0, v.y, wB.y, a0);
            }
            {
                ulonglong2 u = p1[2 * gi], v = p1[2 * gi + 1];
                FMA2(a1, u.x, wA.x, a1); FMA2(a1, u.y, wA.y, a1);
                FMA2(a1, v.x, wB.x, a1); FMA2(a1, v.y, wB.y, a1);
            }
            {
                ulonglong2 u = p2[2 * gi], v = p2[2 * gi + 1];
                FMA2(a2, u.x, wA.x, a2); FMA2(a2, u.y, wA.y, a2);
                FMA2(a2, v.x, wB.x, a2); FMA2(a2, v.y, wB.y, a2);
            }
            {
                ulonglong2 u = p3[2 * gi], v = p3[2 * gi + 1];
                FMA2(a3, u.x, wA.x, a3); FMA2(a3, u.y, wA.y, a3);
                FMA2(a3, v.x, wB.x, a3); FMA2(a3, v.y, wB.y, a3);
            }
            {
                ulonglong2 u = p4[2 * gi], v = p4[2 * gi + 1];
                FMA2(a4, u.x, wA.x, a4); FMA2(a4, u.y, wA.y, a4);
                FMA2(a4, v.x, wB.x, a4); FMA2(a4, v.y, wB.y, a4);
            }
            {
                ulonglong2 u = p5[2 * gi], v = p5[2 * gi + 1];
                FMA2(a5, u.x, wA.x, a5); FMA2(a5, u.y, wA.y, a5);
                FMA2(a5, v.x, wB.x, a5); FMA2(a5, v.y, wB.y, a5);
            }
            {
                ulonglong2 u = p6[2 * gi], v = p6[2 * gi + 1];
                FMA2(a6, u.x, wA.x, a6); FMA2(a6, u.y, wA.y, a6);
                FMA2(a6, v.x, wB.x, a6); FMA2(a6, v.y, wB.y, a6);
            }
            {
                ulonglong2 u = p7[2 * gi], v = p7[2 * gi + 1];
                FMA2(a7, u.x, wA.x, a7); FMA2(a7, u.y, wA.y, a7);
                FMA2(a7, v.x, wB.x, a7); FMA2(a7, v.y, wB.y, a7);
            }
        }

        // ---- fused LN for 8 chains (interleaved shuffles) + guarded stores ----
        ull aa[8] = {a0, a1, a2, a3, a4, a5, a6, a7};
        int rr[8] = {r0, r1, r2, r3, r4, r5, r6, r7};
        float xv[8], yv[8], sv[8], qv[8];
#pragma unroll
        for (int k = 0; k < 8; ++k) {
            xv[k] = lo32(aa[k]); yv[k] = hi32(aa[k]);
            sv[k] = xv[k] + yv[k];
            qv[k] = xv[k] * xv[k] + yv[k] * yv[k];
        }
#pragma unroll
        for (int o = 16; o > 0; o >>= 1) {
#pragma unroll
            for (int k = 0; k < 8; ++k) {
                sv[k] += __shfl_xor_sync(0xffffffffu, sv[k], o);
                qv[k] += __shfl_xor_sync(0xffffffffu, qv[k], o);
            }
        }
#pragma unroll
        for (int k = 0; k < 8; ++k) {
            float mu = sv[k] * (1.f / 64.f);
            float r  = rsqrtf(fmaf(-mu, mu, qv[k] * (1.f / 64.f)) + LN_EPS);
            float2 o2;
            o2.x = fmaf((xv[k] - mu) * r, g2.x, b2.x);
            o2.y = fmaf((yv[k] - mu) * r, g2.y, b2.y);
            if (k < nv) outw[rr[k] * 32] = o2;
        }
    }
}

extern "C" void kernel_launch(void* const* d_in, const int* in_sizes, int n_in,
                              void* d_out, int out_size)
{
    const float* x     = (const float*)d_in[0];
    const float* W     = (const float*)d_in[1];
    const float* Wm    = (const float*)d_in[2];
    const float* gamma = (const float*)d_in[3];
    const float* beta  = (const float*)d_in[4];
    const void*  tmask = d_in[5];
    const void*  smask = d_in[6];

    (void)in_sizes; (void)n_in; (void)out_size;

    cudaFuncSetAttribute(fused_proj_ln_kernel,
                         cudaFuncAttributeMaxDynamicSharedMemorySize, SMEM_TOTAL);

    detect_mask_dtype_kernel<<<1, 1024>>>((const unsigned*)tmask);
    precompute_batch_kernel<<<BB, 32>>>(Wm, smask, gamma, beta);

    const int nblocks = BB * (TT / 128);   // 2048
    fused_proj_ln_kernel<<<nblocks, NTHREADS, SMEM_TOTAL>>>(
        x, W, gamma, beta, tmask, smask, (float*)d_out);
}